// round 3
// baseline (speedup 1.0000x reference)
#include <cuda_runtime.h>
#include <cstdint>

// Problem constants
#define B_ROWS   1024
#define NL       64
#define NH       32
#define NG       20000
#define NC       64
#define GOI      1000
#define LOGIT_N  (GOI * NC)       // 64000
#define EPSV     1e-5f

#define MTILES     (B_ROWS / 128)      // 8
#define LOGIT_BLKS (GOI * MTILES)      // 8000
#define RHO_CTILES ((NG + 63) / 64)    // 313
#define RHO_BLKS   (RHO_CTILES * MTILES) // 2504

#define NG_PAD     20032               // rho rows padded to 64-tile boundary

// Scratch (static device arrays; .bss is zeroed at load — padding rows stay 0)
__device__ float g_h[B_ROWS * NH];          // h: tf32-rounded, k-permuted
__device__ int   g_genes[GOI];
__device__ float g_logitT[GOI * NH * NC];   // gathered gene tables, frag-order
__device__ float g_rhoT[NG_PAD * NH];       // rho_table, frag-order

__device__ __forceinline__ uint32_t tf32r(float x) {
    uint32_t u;
    asm("cvt.rna.tf32.f32 %0, %1;" : "=r"(u) : "f"(x));
    return u;
}

// k-permutation: thread tg's 8 needed k-values become contiguous.
// k = 8*kk + j (j = tg or tg+4)  ->  pos = tg*8 + 2*kk + (j>=4)
__device__ __forceinline__ int kperm(int k) {
    return (k & 3) * 8 + ((k >> 3) << 1) + ((k >> 2) & 1);
}

// n-permutation (within each 16-col group): frag col -> 4 consecutive output cols
// real n = 16P + 4t + 2f + j  ->  frag row = 16P + 8f + 2t + j
__device__ __forceinline__ int p16(int n) {
    return (n & ~15) | ((n & 0x02) << 2) | ((n & 0x0C) >> 1) | (n & 1);
}

__device__ __forceinline__ void mma_tf32(float (&c)[4],
                                         uint32_t a0, uint32_t a1, uint32_t a2, uint32_t a3,
                                         uint32_t b0, uint32_t b1) {
    asm volatile(
        "mma.sync.aligned.m16n8k8.row.col.f32.tf32.tf32.f32 "
        "{%0,%1,%2,%3}, {%4,%5,%6,%7}, {%8,%9}, {%0,%1,%2,%3};"
        : "+f"(c[0]), "+f"(c[1]), "+f"(c[2]), "+f"(c[3])
        : "r"(a0), "r"(a1), "r"(a2), "r"(a3), "r"(b0), "r"(b1));
}

__device__ __forceinline__ uint32_t smem_u32(const void* p) {
    uint32_t a;
    asm("{ .reg .u64 t; cvta.to.shared.u64 t, %1; cvt.u32.u64 %0, t; }"
        : "=r"(a) : "l"(p));
    return a;
}

__device__ __forceinline__ void cp_async16(uint32_t dst, const void* src) {
    asm volatile("cp.async.ca.shared.global [%0], [%1], 16;" :: "r"(dst), "l"(src));
}

// ---------------------------------------------------------------------------
// Kernel 1: gene index normalization (int64 vs int32 detection). 1 block.
// ---------------------------------------------------------------------------
__global__ void detect_genes(const void* __restrict__ genes_raw) {
    __shared__ int odd_zero_cnt;
    if (threadIdx.x == 0) odd_zero_cnt = 0;
    __syncthreads();
    const int* p32 = (const int*)genes_raw;
    int local = 0;
    for (int i = threadIdx.x; i < GOI; i += blockDim.x)
        if ((i & 1) && p32[i] == 0) local++;
    if (local) atomicAdd(&odd_zero_cnt, local);
    __syncthreads();
    bool is64 = (odd_zero_cnt >= 100);
    const long long* p64 = (const long long*)genes_raw;
    for (int i = threadIdx.x; i < GOI; i += blockDim.x) {
        long long v = is64 ? p64[i] : (long long)p32[i];
        if (v < 0) v = 0;
        if (v > NG - 1) v = NG - 1;
        g_genes[i] = (int)v;
    }
}

// ---------------------------------------------------------------------------
// Kernel 2 (prep): blocks [0,128) compute h; [128,1128) gather+permute gene
// tables; [1128,1753) permute rho_table. All outputs tf32-rounded, frag-order.
// ---------------------------------------------------------------------------
__global__ void prep(const float* __restrict__ latent,
                     const float* __restrict__ W,
                     const float* __restrict__ bias,
                     const float* __restrict__ gamma,
                     const float* __restrict__ beta,
                     const float* __restrict__ mean,
                     const float* __restrict__ var,
                     const float* __restrict__ logit_table,
                     const float* __restrict__ rho_table) {
    int bx  = blockIdx.x;
    int tid = threadIdx.x;

    if (bx < 128) {
        // h = relu(BN(latent@W + b)), store tf32-rounded at k-permuted index
        __shared__ float lat_s[8][64];
        __shared__ float w_s[64][32];
        for (int i = tid; i < NL * NH; i += 256)
            w_s[i >> 5][i & 31] = W[i];
        int b0 = bx * 8;
        for (int i = tid; i < 8 * NL; i += 256)
            lat_s[i >> 6][i & 63] = latent[(size_t)b0 * NL + i];
        __syncthreads();

        int br = tid >> 5;
        int j  = tid & 31;
        float s  = rsqrtf(var[j] + EPSV) * gamma[j];
        float sh = fmaf(-mean[j], s, beta[j]);
        sh = fmaf(bias[j], s, sh);
        float acc = 0.f;
#pragma unroll
        for (int l = 0; l < NL; l++)
            acc = fmaf(lat_s[br][l], w_s[l][j], acc);
        float h = fmaxf(0.f, fmaf(acc, s, sh));
        g_h[(b0 + br) * NH + kperm(j)] = __uint_as_float(tf32r(h));
    } else if (bx < 128 + GOI) {
        // gather gene table [k=32][n=64] -> g_logitT[gi][p16(n)*32 + kperm(k)]
        int gi = bx - 128;
        const float* src = logit_table + (size_t)g_genes[gi] * (NH * NC);
        float* dst = g_logitT + (size_t)gi * (NH * NC);
#pragma unroll
        for (int it = 0; it < 8; it++) {
            int i = tid + it * 256;          // coalesced read
            int k = i >> 6, n = i & 63;
            dst[p16(n) * NH + kperm(k)] = __uint_as_float(tf32r(src[i]));
        }
    } else {
        // rho_table rows [n][k=32] -> g_rhoT[p16(n)*32 + kperm(k)]
        int rb = bx - (128 + GOI);           // 625 blocks x 32 rows
        int q  = rb * 256 + tid;             // float4 index
        int n  = q >> 3;
        int k4 = (q & 7) * 4;
        float4 v = *(const float4*)(rho_table + (size_t)n * NH + k4);
        float* dst = g_rhoT + (size_t)p16(n) * NH;
        dst[kperm(k4 + 0)] = __uint_as_float(tf32r(v.x));
        dst[kperm(k4 + 1)] = __uint_as_float(tf32r(v.y));
        dst[kperm(k4 + 2)] = __uint_as_float(tf32r(v.z));
        dst[kperm(k4 + 3)] = __uint_as_float(tf32r(v.w));
    }
}

// ---------------------------------------------------------------------------
// Kernel 3: fused GEMM. CTA tile M=128 x N=64, K=32. 8 warps (4M x 2N),
// warp tile 32x32, acc 32 regs/thread. All staging via cp.async from
// pre-permuted scratch; fragment loads are conflict-free LDS.128.
// ---------------------------------------------------------------------------
__global__ __launch_bounds__(256, 4) void gemm_fused(
        float* __restrict__ out_logit,
        float* __restrict__ out_rho) {
    __shared__ float h_s[128 * 36];
    __shared__ float b_s[64 * 36];

    int tid = threadIdx.x;
    int bx  = blockIdx.x;

    bool is_logit = bx < LOGIT_BLKS;
    int m0, col0, ld, ncols;
    float* out;
    const float* bsrc;

    if (is_logit) {
        int gi = bx >> 3;
        m0    = (bx & 7) * 128;
        col0  = gi * NC;
        ld    = LOGIT_N;
        ncols = LOGIT_N;
        out   = out_logit;
        bsrc  = g_logitT + (size_t)gi * (NH * NC);
    } else {
        int bxr = bx - LOGIT_BLKS;
        int ct  = bxr >> 3;
        m0    = (bxr & 7) * 128;
        col0  = ct * 64;
        ld    = NG;
        ncols = NG;
        out   = out_rho;
        bsrc  = g_rhoT + (size_t)col0 * NH;   // padded rows are zero
    }

    // --- Stage h (128x32) and B (64x32): straight cp.async copies ---
    uint32_t hb = smem_u32(h_s);
    const float* hsrc = g_h + (size_t)m0 * NH;
#pragma unroll
    for (int it = 0; it < 4; it++) {
        int q = tid + it * 256;              // 16B chunk (1024 total)
        int row = q >> 3, seg = q & 7;
        cp_async16(hb + (uint32_t)(row * 36 + seg * 4) * 4, hsrc + q * 4);
    }
    uint32_t bb = smem_u32(b_s);
#pragma unroll
    for (int it = 0; it < 2; it++) {
        int q = tid + it * 256;              // 512 chunks
        int row = q >> 3, seg = q & 7;
        cp_async16(bb + (uint32_t)(row * 36 + seg * 4) * 4, bsrc + q * 4);
    }
    asm volatile("cp.async.commit_group;");
    asm volatile("cp.async.wait_group 0;");
    __syncthreads();

    // --- Mainloop: 16 LDS.128 + 32 MMA per thread ---
    int warp = tid >> 5, lane = tid & 31;
    int g  = lane >> 2, tg = lane & 3;
    int wm = warp >> 1, wn = warp & 1;
    int mb = wm * 32, nb = wn * 32;

    float acc[2][2][2][4];
#pragma unroll
    for (int a = 0; a < 2; a++)
#pragma unroll
        for (int b = 0; b < 2; b++)
#pragma unroll
            for (int c = 0; c < 2; c++)
#pragma unroll
                for (int d = 0; d < 4; d++)
                    acc[a][b][c][d] = 0.f;

    const float4* hu4 = (const float4*)h_s;  // row stride = 9 float4
    const float4* bu4 = (const float4*)b_s;

#pragma unroll
    for (int kk2 = 0; kk2 < 2; kk2++) {
        float4 aLo[2], aHi[2];
#pragma unroll
        for (int mf = 0; mf < 2; mf++) {
            int r = mb + mf * 16 + g;
            aLo[mf] = hu4[r * 9 + tg * 2 + kk2];
            aHi[mf] = hu4[(r + 8) * 9 + tg * 2 + kk2];
        }
#pragma unroll
        for (int p = 0; p < 2; p++)
#pragma unroll
            for (int f = 0; f < 2; f++) {
                int nrow = nb + p * 16 + f * 8 + g;
                float4 b4 = bu4[nrow * 9 + tg * 2 + kk2];
#pragma unroll
                for (int mf = 0; mf < 2; mf++) {
                    mma_tf32(acc[mf][p][f],
                             __float_as_uint(aLo[mf].x), __float_as_uint(aHi[mf].x),
                             __float_as_uint(aLo[mf].y), __float_as_uint(aHi[mf].y),
                             __float_as_uint(b4.x), __float_as_uint(b4.y));
                    mma_tf32(acc[mf][p][f],
                             __float_as_uint(aLo[mf].z), __float_as_uint(aHi[mf].z),
                             __float_as_uint(aLo[mf].w), __float_as_uint(aHi[mf].w),
                             __float_as_uint(b4.z), __float_as_uint(b4.w));
                }
            }
    }

    // --- Epilogue: STG.128 streaming stores, 4 consecutive cols/thread ---
#pragma unroll
    for (int mf = 0; mf < 2; mf++) {
#pragma unroll
        for (int p = 0; p < 2; p++) {
            int row = m0 + mb + mf * 16 + g;
            int col = col0 + nb + p * 16 + 4 * tg;
            if (col < ncols) {
                float4 v0 = make_float4(acc[mf][p][0][0], acc[mf][p][0][1],
                                        acc[mf][p][1][0], acc[mf][p][1][1]);
                float4 v1 = make_float4(acc[mf][p][0][2], acc[mf][p][0][3],
                                        acc[mf][p][1][2], acc[mf][p][1][3]);
                __stcs((float4*)(out + (size_t)row * ld + col), v0);
                __stcs((float4*)(out + (size_t)(row + 8) * ld + col), v1);
            }
        }
    }
}

// ---------------------------------------------------------------------------
// Launch
// ---------------------------------------------------------------------------
extern "C" void kernel_launch(void* const* d_in, const int* in_sizes, int n_in,
                              void* d_out, int out_size) {
    const float* latent      = (const float*)d_in[0];
    const void*  genes_raw   = d_in[1];
    const float* W           = (const float*)d_in[2];
    const float* bias        = (const float*)d_in[3];
    const float* bn_gamma    = (const float*)d_in[4];
    const float* bn_beta     = (const float*)d_in[5];
    const float* bn_mean     = (const float*)d_in[6];
    const float* bn_var      = (const float*)d_in[7];
    const float* logit_table = (const float*)d_in[8];
    const float* rho_table   = (const float*)d_in[9];

    float* out_logit = (float*)d_out;
    float* out_rho   = out_logit + (size_t)B_ROWS * LOGIT_N;

    detect_genes<<<1, 256>>>(genes_raw);
    prep<<<128 + GOI + 625, 256>>>(latent, W, bias, bn_gamma, bn_beta,
                                   bn_mean, bn_var, logit_table, rho_table);
    gemm_fused<<<LOGIT_BLKS + RHO_BLKS, 256>>>(out_logit, out_rho);
}